// round 12
// baseline (speedup 1.0000x reference)
#include <cuda_runtime.h>
#include <cuda_bf16.h>
#include <math.h>
#include <stdint.h>

// Problem dims (fixed by the dataset)
#define BB 64
#define TT 1024
#define FF 256
#define UU 512
#define G4 2048   // 4*U

#define NCTA 128          // phase-2 CTAs (1/SM, co-resident)
#define THR2 512          // 16 warps

// ---------------- device scratch (no cudaMalloc allowed) ----------------
__device__ float g_xz[(size_t)TT * BB * G4];                 // [(t*64+b)][col]
// h broadcast images, XOR-swizzled: [parity][hi/lo][64 rows x 1024B]
// byte offset = row*1024 + ((gran16 ^ (row&7))<<4) + within16
__device__ __align__(16) unsigned char g_hbuf[2][2][BB * 1024];
// per-CTA packed recurrent-weight fragments: [(nt*32+kt)*32+lane][4]
// words = {bhi0, bhi1, blo0, blo1}
__device__ __align__(16) uint32_t g_Bfrag[NCTA][8192];
// phase-1 split operands
__device__ __align__(16) __nv_bfloat16 g_xhl[2][(size_t)BB * TT * FF]; // [b][t][f]
__device__ __align__(16) __nv_bfloat16 g_wt[2][(size_t)G4 * FF];       // [n][k]
__device__ unsigned g_barcount;
__device__ volatile unsigned g_barflag;    // epoch flag, written by last arriver

// ---------------- helpers ----------------
__device__ __forceinline__ uint32_t smem_u32(const void* p) {
    uint32_t a;
    asm("{ .reg .u64 t; cvta.to.shared.u64 t, %1; cvt.u32.u64 %0, t; }"
        : "=r"(a) : "l"(p));
    return a;
}
__device__ __forceinline__ void cp_async16(uint32_t saddr, const void* gaddr) {
    asm volatile("cp.async.cg.shared.global [%0], [%1], 16;" :: "r"(saddr), "l"(gaddr));
}
#define CP_COMMIT() asm volatile("cp.async.commit_group;")
#define CP_WAIT0()  asm volatile("cp.async.wait_group 0;" ::: "memory")

// bulk async copy global->shared, completes on mbarrier (sm_90 base ISA)
__device__ __forceinline__ void bulk_g2s(uint32_t dst, const void* src,
                                         uint32_t bytes, uint32_t mbar) {
    asm volatile(
        "cp.async.bulk.shared::cluster.global.mbarrier::complete_tx::bytes "
        "[%0], [%1], %2, [%3];"
        :: "r"(dst), "l"(src), "r"(bytes), "r"(mbar) : "memory");
}
#define MBAR_INIT(mbar, cnt) \
    asm volatile("mbarrier.init.shared.b64 [%0], %1;" :: "r"(mbar), "r"(cnt) : "memory")
#define MBAR_EXPECT_TX(mbar, bytes) \
    asm volatile("mbarrier.arrive.expect_tx.shared.b64 _, [%0], %1;" \
                 :: "r"(mbar), "r"(bytes) : "memory")

__device__ __forceinline__ void mbar_wait(uint32_t mbar, uint32_t parity) {
    asm volatile(
        "{\n\t.reg .pred P1;\n\t"
        "WL_%=:\n\t"
        "mbarrier.try_wait.parity.acquire.cta.shared::cta.b64 P1, [%0], %1, 0x989680;\n\t"
        "@P1 bra.uni WD_%=;\n\t"
        "bra.uni WL_%=;\n\t"
        "WD_%=:\n\t}"
        :: "r"(mbar), "r"(parity) : "memory");
}

__device__ __forceinline__ void mma_bf16(float c[4], uint32_t a0, uint32_t a1,
                                         uint32_t a2, uint32_t a3,
                                         uint32_t b0, uint32_t b1) {
    asm volatile(
        "mma.sync.aligned.m16n8k16.row.col.f32.bf16.bf16.f32 "
        "{%0,%1,%2,%3}, {%4,%5,%6,%7}, {%8,%9}, {%0,%1,%2,%3};"
        : "+f"(c[0]), "+f"(c[1]), "+f"(c[2]), "+f"(c[3])
        : "r"(a0), "r"(a1), "r"(a2), "r"(a3), "r"(b0), "r"(b1));
}
__device__ __forceinline__ uint4 ldsm4(uint32_t saddr) {
    uint4 r;
    asm volatile("ldmatrix.sync.aligned.m8n8.x4.shared.b16 {%0,%1,%2,%3}, [%4];"
                 : "=r"(r.x), "=r"(r.y), "=r"(r.z), "=r"(r.w) : "r"(saddr));
    return r;
}
__device__ __forceinline__ void split_bf16(float v, uint16_t& hi, uint16_t& lo) {
    __nv_bfloat16 h = __float2bfloat16(v);
    __nv_bfloat16 l = __float2bfloat16(v - __bfloat162float(h));
    hi = *(uint16_t*)&h; lo = *(uint16_t*)&l;
}

// ---------------- init ----------------
__global__ void init_kernel() {
    int i = blockIdx.x * blockDim.x + threadIdx.x;
    if (i == 0) { g_barcount = 0u; g_barflag = 0u; }
    uint32_t* p = (uint32_t*)g_hbuf;  // 2*2*64*1024 bytes = 65536 words
    for (int j = i; j < 65536; j += gridDim.x * blockDim.x) p[j] = 0u;
}

// ---------------- prep: split X (fp32 -> hi/lo bf16) ----------------
__global__ void prep_X(const float* __restrict__ x) {
    const size_t N = (size_t)BB * TT * FF;
    size_t stride = (size_t)gridDim.x * blockDim.x;
    for (size_t j = blockIdx.x * blockDim.x + threadIdx.x; j < N; j += stride) {
        uint16_t hi, lo;
        split_bf16(x[j], hi, lo);
        *(uint16_t*)&g_xhl[0][j] = hi;
        *(uint16_t*)&g_xhl[1][j] = lo;
    }
}

// ---------------- prep: split + transpose W -> [n][k] ----------------
__global__ void prep_W(const float* __restrict__ w) {
    const int N = G4 * FF;
    int stride = gridDim.x * blockDim.x;
    for (int j = blockIdx.x * blockDim.x + threadIdx.x; j < N; j += stride) {
        int n = j >> 8, k = j & 255;
        uint16_t hi, lo;
        split_bf16(w[(size_t)k * G4 + n], hi, lo);
        *(uint16_t*)&g_wt[0][j] = hi;
        *(uint16_t*)&g_wt[1][j] = lo;
    }
}

// ---------------- prep: recurrent weight fragments (packed) -------------
// CTA j owns units [4j,4j+4). n = nt*8 + g (g=lane>>2); gate = n>>2, u = n&3;
// global col = gate*512 + 4j + u.  k = kt*16 + tq*2 + w2*8 (tq=lane&3).
__global__ void prep_B(const float* __restrict__ R) {
    const int j = blockIdx.x;
    uint32_t* dst = g_Bfrag[j];
    for (int widx = threadIdx.x; widx < 8192; widx += blockDim.x) {
        int w     = widx & 3;
        int lane  = (widx >> 2) & 31;
        int kt    = (widx >> 7) & 31;
        int nt    = widx >> 12;
        int plane = w >> 1, w2 = w & 1;
        int g = lane >> 2, tq = lane & 3;
        int k = kt * 16 + tq * 2 + w2 * 8;
        int n = nt * 8 + g;
        int col = (n >> 2) * 512 + j * 4 + (n & 3);
        float v0 = R[(size_t)k * G4 + col];
        float v1 = R[(size_t)(k + 1) * G4 + col];
        uint16_t h0, l0, h1, l1;
        split_bf16(v0, h0, l0);
        split_bf16(v1, h1, l1);
        uint16_t a = plane ? l0 : h0, b = plane ? l1 : h1;
        dst[widx] = ((uint32_t)b << 16) | a;
    }
}

// ---------------- phase 1: xz = x @ kernel + bias  (mma.sync bf16 split) --
#define X1_AS   272
#define X1_APL  34816
#define X1_SMEM (4 * 34816)

__global__ __launch_bounds__(256, 1) void xz_mma(const float* __restrict__ bias) {
    extern __shared__ char sm1[];
    const int tid  = threadIdx.x;
    const int lane = tid & 31;
    const int warp = tid >> 5;
    const int wm = warp >> 2, wn = warp & 3;
    const int mbase = blockIdx.y * 128, nbase = blockIdx.x * 128;
    const uint32_t smB = smem_u32(sm1);
    const uint32_t smAhi = smB, smAlo = smB + X1_APL;
    const uint32_t smBhi = smB + 2 * X1_APL, smBlo = smB + 3 * X1_APL;

    float c[4][4][4];
#pragma unroll
    for (int mi = 0; mi < 4; mi++)
#pragma unroll
        for (int ni = 0; ni < 4; ni++)
#pragma unroll
            for (int q = 0; q < 4; q++) c[mi][ni][q] = 0.f;

    const int rowA = (lane & 7) + ((lane >> 3) & 1) * 8;
    const int kbA  = ((lane >> 4) & 1) * 16;
    const int mB   = lane >> 3;
    const int rowB = ((mB >> 1) & 1) * 8 + (lane & 7);
    const int kbB  = (mB & 1) * 16;
    const int srow0 = tid >> 4;
    const int kg    = tid & 15;

    for (int ch = 0; ch < 2; ch++) {
#pragma unroll
        for (int s = 0; s < 8; s++) {
            int row = srow0 + s * 16;
            int m = mbase + row;
            int b = m & 63, tt = m >> 6;
            size_t offA = ((size_t)(b << 10) + tt) * 256 + ch * 128 + kg * 8;
            uint32_t d = row * X1_AS + kg * 16;
            cp_async16(smAhi + d, &g_xhl[0][offA]);
            cp_async16(smAlo + d, &g_xhl[1][offA]);
            size_t offB = (size_t)(nbase + row) * 256 + ch * 128 + kg * 8;
            cp_async16(smBhi + d, &g_wt[0][offB]);
            cp_async16(smBlo + d, &g_wt[1][offB]);
        }
        CP_COMMIT(); CP_WAIT0();
        __syncthreads();

#pragma unroll
        for (int kt = 0; kt < 8; kt++) {
            uint4 ah[4], al[4];
#pragma unroll
            for (int mi = 0; mi < 4; mi++) {
                uint32_t ar = (wm * 64 + mi * 16 + rowA) * X1_AS + kbA + kt * 32;
                ah[mi] = ldsm4(smAhi + ar);
                al[mi] = ldsm4(smAlo + ar);
            }
            uint32_t br0 = (wn * 32 + rowB) * X1_AS + kbB + kt * 32;
            uint32_t br1 = (wn * 32 + 16 + rowB) * X1_AS + kbB + kt * 32;
            uint4 bh01 = ldsm4(smBhi + br0);
            uint4 bh23 = ldsm4(smBhi + br1);
            uint4 bl01 = ldsm4(smBlo + br0);
            uint4 bl23 = ldsm4(smBlo + br1);
#pragma unroll
            for (int mi = 0; mi < 4; mi++) {
                mma_bf16(c[mi][0], ah[mi].x, ah[mi].y, ah[mi].z, ah[mi].w, bh01.x, bh01.y);
                mma_bf16(c[mi][0], ah[mi].x, ah[mi].y, ah[mi].z, ah[mi].w, bl01.x, bl01.y);
                mma_bf16(c[mi][0], al[mi].x, al[mi].y, al[mi].z, al[mi].w, bh01.x, bh01.y);
                mma_bf16(c[mi][1], ah[mi].x, ah[mi].y, ah[mi].z, ah[mi].w, bh01.z, bh01.w);
                mma_bf16(c[mi][1], ah[mi].x, ah[mi].y, ah[mi].z, ah[mi].w, bl01.z, bl01.w);
                mma_bf16(c[mi][1], al[mi].x, al[mi].y, al[mi].z, al[mi].w, bh01.z, bh01.w);
                mma_bf16(c[mi][2], ah[mi].x, ah[mi].y, ah[mi].z, ah[mi].w, bh23.x, bh23.y);
                mma_bf16(c[mi][2], ah[mi].x, ah[mi].y, ah[mi].z, ah[mi].w, bl23.x, bl23.y);
                mma_bf16(c[mi][2], al[mi].x, al[mi].y, al[mi].z, al[mi].w, bh23.x, bh23.y);
                mma_bf16(c[mi][3], ah[mi].x, ah[mi].y, ah[mi].z, ah[mi].w, bh23.z, bh23.w);
                mma_bf16(c[mi][3], ah[mi].x, ah[mi].y, ah[mi].z, ah[mi].w, bl23.z, bl23.w);
                mma_bf16(c[mi][3], al[mi].x, al[mi].y, al[mi].z, al[mi].w, bh23.z, bh23.w);
            }
        }
        __syncthreads();
    }

    const int g = lane >> 2, tq = lane & 3;
#pragma unroll
    for (int ni = 0; ni < 4; ni++) {
        int col = nbase + wn * 32 + ni * 8 + tq * 2;
        float bx = bias[col], by = bias[col + 1];
#pragma unroll
        for (int mi = 0; mi < 4; mi++) {
            int row = mbase + wm * 64 + mi * 16 + g;
            float2 v0 = {c[mi][ni][0] + bx, c[mi][ni][1] + by};
            float2 v1 = {c[mi][ni][2] + bx, c[mi][ni][3] + by};
            *(float2*)&g_xz[(size_t)row * G4 + col] = v0;
            *(float2*)&g_xz[(size_t)(row + 8) * G4 + col] = v1;
        }
    }
}

// ---------------- phase 2: persistent mma.sync recurrence (128 CTAs) -----
// SMEM map (bytes, relative to dynamic base):
//   A hi image : [0, 64K)    64 rows x 1024B, XOR-swizzled (linear bulk copy)
//   A lo image : [64K, 128K)
//   B frags    : [128K, 160K)
//   zbuf       : [160K, +22528)  [4 kq][64][22] f32  (EVEN stride: float2-safe)
#define SM_HHI     0
#define SM_HLO     65536
#define SM_B       131072
#define SM_Z       163840
#define Z_S        22
#define SMEM_DYN   186368

__global__ __launch_bounds__(THR2, 1) void lstm_rec(float* __restrict__ out)
{
    extern __shared__ char sm[];
    __shared__ __align__(8) uint64_t sh_mb[4];

    const int tid  = threadIdx.x;
    const int lane = tid & 31;
    const int warp = tid >> 5;
    const int cta  = blockIdx.x;
    const int kq = warp >> 2;           // k-quarter 0..3
    const int mt = warp & 3;            // batch tile 0..3 (= h chunk id)

    const uint32_t smBase = smem_u32(sm);
    uint32_t mb[4];
#pragma unroll
    for (int m = 0; m < 4; m++) mb[m] = smem_u32(&sh_mb[m]);
    if (tid == 0) {
#pragma unroll
        for (int m = 0; m < 4; m++) MBAR_INIT(mb[m], 1u);
    }

    // ---- load resident B fragments (32KB) ----
    {
        const uint32_t* src = g_Bfrag[cta];
        for (int i = tid; i < 2048; i += THR2)
            cp_async16(smBase + SM_B + i * 16, src + i * 4);
        CP_COMMIT(); CP_WAIT0();
    }
    __syncthreads();

    // ---- initial bulk issue for t=0 (h = zeros, init'd) ----
    if (tid == 0) {
#pragma unroll
        for (int m = 0; m < 4; m++) {
            MBAR_EXPECT_TX(mb[m], 32768u);
            bulk_g2s(smBase + SM_HHI + m * 16384, &g_hbuf[0][0][m * 16384],
                     16384u, mb[m]);
            bulk_g2s(smBase + SM_HLO + m * 16384, &g_hbuf[0][1][m * 16384],
                     16384u, mb[m]);
        }
    }

    // ---- ldmatrix lane bases (swizzled A image) ----
    const int rowA = (lane & 7) + ((lane >> 3) & 1) * 8;
    const int kbIdx = (lane >> 4) & 1;          // granule half within ktile
    const int arow  = mt * 16 + rowA;
    const uint32_t aRowHi = smBase + SM_HHI + arow * 1024;
    const uint32_t aRowLo = smBase + SM_HLO + arow * 1024;
    const uint32_t rxor = (uint32_t)(arow & 7);
    float* zb = (float*)(sm + SM_Z);
    const int g = lane >> 2, tq = lane & 3;
    // hoisted B-fragment bases for this warp (nt=0/1)
    const char* bP0 = sm + SM_B + (0 * 32 + kq * 8) * 512 + lane * 16;
    const char* bP1 = sm + SM_B + (1 * 32 + kq * 8) * 512 + lane * 16;

    // epilogue constants: 128 threads, thread = (batch, unit-half)
    const int eb = tid & 63;            // batch
    const int uh = tid >> 6;            // unit half: units uh*2..uh*2+2
    float cst[2] = {0.f, 0.f};

    for (int t = 0; t < TT; t++) {
        const int p = t & 1;

        // xz prefetch for epilogue threads (overlaps chunk waits / mma)
        float2 xz2[4];
        if (tid < 128) {
            const float* xzt = &g_xz[((size_t)t * BB + eb) * G4 + cta * 4 + uh * 2];
#pragma unroll
            for (int gate = 0; gate < 4; gate++)
                xz2[gate] = *(const float2*)&xzt[gate * 512];
        }

        // wait for this warp's 16-row chunk of h
        mbar_wait(mb[mt], (uint32_t)(t & 1));

        // ---- mma: 8 ktiles (this warp's k-quarter), 2 nt, 3 split terms ---
        float c[2][4];
#pragma unroll
        for (int nt = 0; nt < 2; nt++)
#pragma unroll
            for (int q = 0; q < 4; q++) c[nt][q] = 0.f;

#pragma unroll
        for (int ktl = 0; ktl < 8; ktl++) {
            const int kt = kq * 8 + ktl;
            const uint32_t goff = (((uint32_t)(kt * 2 + kbIdx)) ^ rxor) << 4;
            uint4 ah = ldsm4(aRowHi + goff);
            uint4 al = ldsm4(aRowLo + goff);
            uint4 b0 = *(const uint4*)(bP0 + ktl * 512);
            uint4 b1 = *(const uint4*)(bP1 + ktl * 512);
            mma_bf16(c[0], ah.x, ah.y, ah.z, ah.w, b0.x, b0.y);  // AhiBhi
            mma_bf16(c[0], ah.x, ah.y, ah.z, ah.w, b0.z, b0.w);  // AhiBlo
            mma_bf16(c[0], al.x, al.y, al.z, al.w, b0.x, b0.y);  // AloBhi
            mma_bf16(c[1], ah.x, ah.y, ah.z, ah.w, b1.x, b1.y);
            mma_bf16(c[1], ah.x, ah.y, ah.z, ah.w, b1.z, b1.w);
            mma_bf16(c[1], al.x, al.y, al.z, al.w, b1.x, b1.y);
        }

        // store partials: zbuf[kq][row][col]  (even stride -> 8B aligned)
#pragma unroll
        for (int nt = 0; nt < 2; nt++) {
            int r0 = mt * 16 + g, cc = nt * 8 + tq * 2;
            float2 v01 = {c[nt][0], c[nt][1]};
            float2 v23 = {c[nt][2], c[nt][3]};
            *(float2*)&zb[(kq * 64 + r0) * Z_S + cc] = v01;
            *(float2*)&zb[(kq * 64 + r0 + 8) * Z_S + cc] = v23;
        }
        __syncthreads();

        // ---- epilogue part 1: gates, c-state, h store (critical path) ----
        float hv[2];
        if (tid < 128) {
            float q[4][2];
#pragma unroll
            for (int gate = 0; gate < 4; gate++) {
                q[gate][0] = xz2[gate].x;
                q[gate][1] = xz2[gate].y;
#pragma unroll
                for (int kk = 0; kk < 4; kk++) {
                    float2 z = *(const float2*)&zb[(kk * 64 + eb) * Z_S + gate * 4 + uh * 2];
                    q[gate][0] += z.x;
                    q[gate][1] += z.y;
                }
            }
            uint16_t hh[2], hl[2];
#pragma unroll
            for (int u = 0; u < 2; u++) {
                float ig = 1.f / (1.f + __expf(-q[0][u]));
                float fg = 1.f / (1.f + __expf(-q[1][u]));
                float og = 1.f / (1.f + __expf(-q[3][u]));
                cst[u] = fg * cst[u] + ig * q[2][u];
                hv[u] = og * cst[u];
                split_bf16(hv[u], hh[u], hl[u]);
            }
            unsigned vhi = ((uint32_t)hh[1] << 16) | hh[0];
            unsigned vlo = ((uint32_t)hl[1] << 16) | hl[0];
            const int pn = p ^ 1;
            // swizzled h-image store: row=eb, granule=(cta>>1)^(eb&7),
            // 8B half=(cta&1), 4B quarter=uh
            uint32_t off = (uint32_t)eb * 1024 +
                           ((((uint32_t)cta >> 1) ^ ((uint32_t)eb & 7)) << 4) +
                           ((uint32_t)cta & 1) * 8 + (uint32_t)uh * 4;
            __stcg((unsigned*)(&g_hbuf[pn][0][0] + off), vhi);
            __stcg((unsigned*)(&g_hbuf[pn][1][0] + off), vlo);
        }
        __syncthreads();   // all h stores issued before arrival

        // ---- barrier arrival (flag-broadcast) ----
        if (tid == 0) {
            __threadfence();
            unsigned arrived = atomicAdd(&g_barcount, 1u) + 1u;
            if (arrived == ((unsigned)(t + 1) << 7))   // *128
                g_barflag = (unsigned)(t + 1);
        }

        // ---- epilogue part 2: tanh + out store, in the wait shadow ----
        if (tid < 128) {
            float2 o2 = {tanhf(hv[0]), tanhf(hv[1])};
            *(float2*)&out[((size_t)eb * TT + t) * UU + cta * 4 + uh * 2] = o2;
        }

        // ---- wait for epoch flag; issue next step's bulk copies ----
        if (tid == 0) {
            while (g_barflag < (unsigned)(t + 1)) { }
            if (t + 1 < TT) {
                const int np = (t + 1) & 1;
#pragma unroll
                for (int m = 0; m < 4; m++) {
                    MBAR_EXPECT_TX(mb[m], 32768u);
                    bulk_g2s(smBase + SM_HHI + m * 16384,
                             &g_hbuf[np][0][m * 16384], 16384u, mb[m]);
                    bulk_g2s(smBase + SM_HLO + m * 16384,
                             &g_hbuf[np][1][m * 16384], 16384u, mb[m]);
                }
            }
        }
        __syncthreads();
    }
}

// ---------------- launch ----------------
extern "C" void kernel_launch(void* const* d_in, const int* in_sizes, int n_in,
                              void* d_out, int out_size) {
    const float* x    = (const float*)d_in[0];   // [64,1024,256]
    const float* w    = (const float*)d_in[1];   // [256,2048]
    const float* rw   = (const float*)d_in[2];   // [512,2048]
    const float* bias = (const float*)d_in[3];   // [2048]
    float* out = (float*)d_out;                  // [64,1024,512]
    (void)in_sizes; (void)n_in; (void)out_size;

    init_kernel<<<64, 256>>>();
    prep_X<<<4096, 256>>>(x);
    prep_W<<<512, 256>>>(w);
    prep_B<<<NCTA, 256>>>(rw);

    static int smem_set = 0;
    if (!smem_set) {
        cudaFuncSetAttribute(xz_mma, cudaFuncAttributeMaxDynamicSharedMemorySize,
                             X1_SMEM);
        cudaFuncSetAttribute(lstm_rec, cudaFuncAttributeMaxDynamicSharedMemorySize,
                             SMEM_DYN);
        smem_set = 1;
    }

    dim3 g1(G4 / 128, (BB * TT) / 128);   // (16, 512)
    xz_mma<<<g1, 256, X1_SMEM>>>(bias);

    lstm_rec<<<NCTA, THR2, SMEM_DYN>>>(out);
}

// round 14
// speedup vs baseline: 1.0734x; 1.0734x over previous
#include <cuda_runtime.h>
#include <cuda_bf16.h>
#include <math.h>
#include <stdint.h>

// Problem dims (fixed by the dataset)
#define BB 64
#define TT 1024
#define FF 256
#define UU 512
#define G4 2048   // 4*U

#define NCTA 128          // phase-2 CTAs (1/SM, co-resident)
#define THR2 512          // 16 warps

// ---------------- device scratch (no cudaMalloc allowed) ----------------
__device__ float g_xz[(size_t)TT * BB * G4];                 // [(t*64+b)][col]
// h broadcast images, XOR-swizzled: [parity][hi/lo][64 rows x 1024B]
// byte offset = row*1024 + ((gran16 ^ (row&7))<<4) + within16
__device__ __align__(16) unsigned char g_hbuf[2][2][BB * 1024];
// per-CTA packed recurrent-weight fragments: [(nt*32+kt)*32+lane][4]
// words = {bhi0, bhi1, blo0, blo1}
__device__ __align__(16) uint32_t g_Bfrag[NCTA][8192];
// phase-1 split operands
__device__ __align__(16) __nv_bfloat16 g_xhl[2][(size_t)BB * TT * FF]; // [b][t][f]
__device__ __align__(16) __nv_bfloat16 g_wt[2][(size_t)G4 * FF];       // [n][k]
__device__ unsigned g_barcount;

// ---------------- helpers ----------------
__device__ __forceinline__ uint32_t smem_u32(const void* p) {
    uint32_t a;
    asm("{ .reg .u64 t; cvta.to.shared.u64 t, %1; cvt.u32.u64 %0, t; }"
        : "=r"(a) : "l"(p));
    return a;
}
__device__ __forceinline__ void cp_async16(uint32_t saddr, const void* gaddr) {
    asm volatile("cp.async.cg.shared.global [%0], [%1], 16;" :: "r"(saddr), "l"(gaddr));
}
#define CP_COMMIT() asm volatile("cp.async.commit_group;")
#define CP_WAIT0()  asm volatile("cp.async.wait_group 0;" ::: "memory")

// bulk async copy global->shared, completes on mbarrier (sm_90 base ISA)
__device__ __forceinline__ void bulk_g2s(uint32_t dst, const void* src,
                                         uint32_t bytes, uint32_t mbar) {
    asm volatile(
        "cp.async.bulk.shared::cluster.global.mbarrier::complete_tx::bytes "
        "[%0], [%1], %2, [%3];"
        :: "r"(dst), "l"(src), "r"(bytes), "r"(mbar) : "memory");
}
#define MBAR_INIT(mbar, cnt) \
    asm volatile("mbarrier.init.shared.b64 [%0], %1;" :: "r"(mbar), "r"(cnt) : "memory")
#define MBAR_EXPECT_TX(mbar, bytes) \
    asm volatile("mbarrier.arrive.expect_tx.shared.b64 _, [%0], %1;" \
                 :: "r"(mbar), "r"(bytes) : "memory")

__device__ __forceinline__ void mbar_wait(uint32_t mbar, uint32_t parity) {
    asm volatile(
        "{\n\t.reg .pred P1;\n\t"
        "WL_%=:\n\t"
        "mbarrier.try_wait.parity.acquire.cta.shared::cta.b64 P1, [%0], %1, 0x989680;\n\t"
        "@P1 bra.uni WD_%=;\n\t"
        "bra.uni WL_%=;\n\t"
        "WD_%=:\n\t}"
        :: "r"(mbar), "r"(parity) : "memory");
}

__device__ __forceinline__ void mma_bf16(float c[4], uint32_t a0, uint32_t a1,
                                         uint32_t a2, uint32_t a3,
                                         uint32_t b0, uint32_t b1) {
    asm volatile(
        "mma.sync.aligned.m16n8k16.row.col.f32.bf16.bf16.f32 "
        "{%0,%1,%2,%3}, {%4,%5,%6,%7}, {%8,%9}, {%0,%1,%2,%3};"
        : "+f"(c[0]), "+f"(c[1]), "+f"(c[2]), "+f"(c[3])
        : "r"(a0), "r"(a1), "r"(a2), "r"(a3), "r"(b0), "r"(b1));
}
__device__ __forceinline__ uint4 ldsm4(uint32_t saddr) {
    uint4 r;
    asm volatile("ldmatrix.sync.aligned.m8n8.x4.shared.b16 {%0,%1,%2,%3}, [%4];"
                 : "=r"(r.x), "=r"(r.y), "=r"(r.z), "=r"(r.w) : "r"(saddr));
    return r;
}
__device__ __forceinline__ void split_bf16(float v, uint16_t& hi, uint16_t& lo) {
    __nv_bfloat16 h = __float2bfloat16(v);
    __nv_bfloat16 l = __float2bfloat16(v - __bfloat162float(h));
    hi = *(uint16_t*)&h; lo = *(uint16_t*)&l;
}

// ---------------- prep_misc: init + X split + W split (one launch) ------
// blocks [0,4096): X split (blocks [0,64) additionally reset h/barrier)
// blocks [4096,4608): W split+transpose
__global__ void prep_misc(const float* __restrict__ x,
                          const float* __restrict__ w) {
    const int b = blockIdx.x;
    if (b < 4096) {
        size_t i = (size_t)b * 256 + threadIdx.x;
        const size_t N = (size_t)BB * TT * FF;
        for (size_t j = i; j < N; j += (size_t)4096 * 256) {
            uint16_t hi, lo;
            split_bf16(x[j], hi, lo);
            *(uint16_t*)&g_xhl[0][j] = hi;
            *(uint16_t*)&g_xhl[1][j] = lo;
        }
        if (b < 64) {
            int ii = b * 256 + threadIdx.x;
            if (ii == 0) g_barcount = 0u;
            uint32_t* p = (uint32_t*)g_hbuf;   // 65536 words
            for (int j = ii; j < 65536; j += 64 * 256) p[j] = 0u;
        }
    } else {
        int i = (b - 4096) * 256 + threadIdx.x;
        for (int j = i; j < G4 * FF; j += 512 * 256) {
            int n = j >> 8, k = j & 255;
            uint16_t hi, lo;
            split_bf16(w[(size_t)k * G4 + n], hi, lo);
            *(uint16_t*)&g_wt[0][j] = hi;
            *(uint16_t*)&g_wt[1][j] = lo;
        }
    }
}

// ---------------- prep_B: recurrent weight fragments (packed) -----------
// CTA j owns units [4j,4j+4). n = nt*8 + g (g=lane>>2); gate = n>>2, u = n&3;
// global col = gate*512 + 4j + u.  k = kt*16 + tq*2 + w2*8 (tq=lane&3).
__global__ void prep_B(const float* __restrict__ R) {
    const int j = blockIdx.x;
    uint32_t* dst = g_Bfrag[j];
    for (int widx = threadIdx.x; widx < 8192; widx += blockDim.x) {
        int w     = widx & 3;
        int lane  = (widx >> 2) & 31;
        int kt    = (widx >> 7) & 31;
        int nt    = widx >> 12;
        int plane = w >> 1, w2 = w & 1;
        int g = lane >> 2, tq = lane & 3;
        int k = kt * 16 + tq * 2 + w2 * 8;
        int n = nt * 8 + g;
        int col = (n >> 2) * 512 + j * 4 + (n & 3);
        float v0 = R[(size_t)k * G4 + col];
        float v1 = R[(size_t)(k + 1) * G4 + col];
        uint16_t h0, l0, h1, l1;
        split_bf16(v0, h0, l0);
        split_bf16(v1, h1, l1);
        uint16_t a = plane ? l0 : h0, bq = plane ? l1 : h1;
        dst[widx] = ((uint32_t)bq << 16) | a;
    }
}

// ---------------- phase 1: xz = x @ kernel + bias  (mma.sync bf16 split) --
#define X1_AS   272
#define X1_APL  34816
#define X1_SMEM (4 * 34816)

__global__ __launch_bounds__(256, 1) void xz_mma(const float* __restrict__ bias) {
    extern __shared__ char sm1[];
    const int tid  = threadIdx.x;
    const int lane = tid & 31;
    const int warp = tid >> 5;
    const int wm = warp >> 2, wn = warp & 3;
    const int mbase = blockIdx.y * 128, nbase = blockIdx.x * 128;
    const uint32_t smB = smem_u32(sm1);
    const uint32_t smAhi = smB, smAlo = smB + X1_APL;
    const uint32_t smBhi = smB + 2 * X1_APL, smBlo = smB + 3 * X1_APL;

    float c[4][4][4];
#pragma unroll
    for (int mi = 0; mi < 4; mi++)
#pragma unroll
        for (int ni = 0; ni < 4; ni++)
#pragma unroll
            for (int q = 0; q < 4; q++) c[mi][ni][q] = 0.f;

    const int rowA = (lane & 7) + ((lane >> 3) & 1) * 8;
    const int kbA  = ((lane >> 4) & 1) * 16;
    const int mB   = lane >> 3;
    const int rowB = ((mB >> 1) & 1) * 8 + (lane & 7);
    const int kbB  = (mB & 1) * 16;
    const int srow0 = tid >> 4;
    const int kg    = tid & 15;

    for (int ch = 0; ch < 2; ch++) {
#pragma unroll
        for (int s = 0; s < 8; s++) {
            int row = srow0 + s * 16;
            int m = mbase + row;
            int b = m & 63, tt = m >> 6;
            size_t offA = ((size_t)(b << 10) + tt) * 256 + ch * 128 + kg * 8;
            uint32_t d = row * X1_AS + kg * 16;
            cp_async16(smAhi + d, &g_xhl[0][offA]);
            cp_async16(smAlo + d, &g_xhl[1][offA]);
            size_t offB = (size_t)(nbase + row) * 256 + ch * 128 + kg * 8;
            cp_async16(smBhi + d, &g_wt[0][offB]);
            cp_async16(smBlo + d, &g_wt[1][offB]);
        }
        CP_COMMIT(); CP_WAIT0();
        __syncthreads();

#pragma unroll
        for (int kt = 0; kt < 8; kt++) {
            uint4 ah[4], al[4];
#pragma unroll
            for (int mi = 0; mi < 4; mi++) {
                uint32_t ar = (wm * 64 + mi * 16 + rowA) * X1_AS + kbA + kt * 32;
                ah[mi] = ldsm4(smAhi + ar);
                al[mi] = ldsm4(smAlo + ar);
            }
            uint32_t br0 = (wn * 32 + rowB) * X1_AS + kbB + kt * 32;
            uint32_t br1 = (wn * 32 + 16 + rowB) * X1_AS + kbB + kt * 32;
            uint4 bh01 = ldsm4(smBhi + br0);
            uint4 bh23 = ldsm4(smBhi + br1);
            uint4 bl01 = ldsm4(smBlo + br0);
            uint4 bl23 = ldsm4(smBlo + br1);
#pragma unroll
            for (int mi = 0; mi < 4; mi++) {
                mma_bf16(c[mi][0], ah[mi].x, ah[mi].y, ah[mi].z, ah[mi].w, bh01.x, bh01.y);
                mma_bf16(c[mi][0], ah[mi].x, ah[mi].y, ah[mi].z, ah[mi].w, bl01.x, bl01.y);
                mma_bf16(c[mi][0], al[mi].x, al[mi].y, al[mi].z, al[mi].w, bh01.x, bh01.y);
                mma_bf16(c[mi][1], ah[mi].x, ah[mi].y, ah[mi].z, ah[mi].w, bh01.z, bh01.w);
                mma_bf16(c[mi][1], ah[mi].x, ah[mi].y, ah[mi].z, ah[mi].w, bl01.z, bl01.w);
                mma_bf16(c[mi][1], al[mi].x, al[mi].y, al[mi].z, al[mi].w, bh01.z, bh01.w);
                mma_bf16(c[mi][2], ah[mi].x, ah[mi].y, ah[mi].z, ah[mi].w, bh23.x, bh23.y);
                mma_bf16(c[mi][2], ah[mi].x, ah[mi].y, ah[mi].z, ah[mi].w, bl23.x, bl23.y);
                mma_bf16(c[mi][2], al[mi].x, al[mi].y, al[mi].z, al[mi].w, bh23.x, bh23.y);
                mma_bf16(c[mi][3], ah[mi].x, ah[mi].y, ah[mi].z, ah[mi].w, bh23.z, bh23.w);
                mma_bf16(c[mi][3], ah[mi].x, ah[mi].y, ah[mi].z, ah[mi].w, bl23.z, bl23.w);
                mma_bf16(c[mi][3], al[mi].x, al[mi].y, al[mi].z, al[mi].w, bh23.z, bh23.w);
            }
        }
        __syncthreads();
    }

    const int g = lane >> 2, tq = lane & 3;
#pragma unroll
    for (int ni = 0; ni < 4; ni++) {
        int col = nbase + wn * 32 + ni * 8 + tq * 2;
        float bx = bias[col], by = bias[col + 1];
#pragma unroll
        for (int mi = 0; mi < 4; mi++) {
            int row = mbase + wm * 64 + mi * 16 + g;
            float2 v0 = {c[mi][ni][0] + bx, c[mi][ni][1] + by};
            float2 v1 = {c[mi][ni][2] + bx, c[mi][ni][3] + by};
            *(float2*)&g_xz[(size_t)row * G4 + col] = v0;
            *(float2*)&g_xz[(size_t)(row + 8) * G4 + col] = v1;
        }
    }
}

// ---------------- phase 2: persistent mma.sync recurrence (128 CTAs) -----
// SMEM map (bytes, relative to dynamic base):
//   A hi image : [0, 64K)    64 rows x 1024B, XOR-swizzled (linear bulk copy)
//   A lo image : [64K, 128K)
//   B frags    : [128K, 160K)
//   zbuf       : [160K, +22528)  [4 kq][64][22] f32  (EVEN stride: float2-safe)
#define SM_HHI     0
#define SM_HLO     65536
#define SM_B       131072
#define SM_Z       163840
#define Z_S        22
#define SMEM_DYN   186368

__global__ __launch_bounds__(THR2, 1) void lstm_rec(float* __restrict__ out)
{
    extern __shared__ char sm[];
    __shared__ __align__(8) uint64_t sh_mb[4];

    const int tid  = threadIdx.x;
    const int lane = tid & 31;
    const int warp = tid >> 5;
    const int cta  = blockIdx.x;
    const int kq = warp >> 2;           // k-quarter 0..3
    const int mt = warp & 3;            // batch tile 0..3 (= h chunk id)

    const uint32_t smBase = smem_u32(sm);
    uint32_t mb[4];
#pragma unroll
    for (int m = 0; m < 4; m++) mb[m] = smem_u32(&sh_mb[m]);
    if (tid == 0) {
#pragma unroll
        for (int m = 0; m < 4; m++) MBAR_INIT(mb[m], 1u);
    }

    // ---- load resident B fragments (32KB) ----
    {
        const uint32_t* src = g_Bfrag[cta];
        for (int i = tid; i < 2048; i += THR2)
            cp_async16(smBase + SM_B + i * 16, src + i * 4);
        CP_COMMIT(); CP_WAIT0();
    }
    __syncthreads();

    // ---- ldmatrix lane bases (swizzled A image) ----
    const int rowA = (lane & 7) + ((lane >> 3) & 1) * 8;
    const int kbIdx = (lane >> 4) & 1;          // granule half within ktile
    const int arow  = mt * 16 + rowA;
    const uint32_t aRowHi = smBase + SM_HHI + arow * 1024;
    const uint32_t aRowLo = smBase + SM_HLO + arow * 1024;
    const uint32_t rxor = (uint32_t)(arow & 7);
    float* zb = (float*)(sm + SM_Z);
    const int g = lane >> 2, tq = lane & 3;
    // hoisted B-fragment bases for this warp (nt=0/1)
    const char* bP0 = sm + SM_B + (0 * 32 + kq * 8) * 512 + lane * 16;
    const char* bP1 = sm + SM_B + (1 * 32 + kq * 8) * 512 + lane * 16;

    // epilogue constants: 128 threads, thread = (batch, unit-half)
    const int eb = tid & 63;            // batch
    const int uh = tid >> 6;            // unit half: units uh*2..uh*2+2
    float cst[2] = {0.f, 0.f};

    for (int t = 0; t < TT; t++) {
        const int p = t & 1;

        // issue 4 row-chunk bulk copies of h (hi+lo), one mbar per chunk
        if (tid == 0) {
#pragma unroll
            for (int m = 0; m < 4; m++) {
                MBAR_EXPECT_TX(mb[m], 32768u);
                bulk_g2s(smBase + SM_HHI + m * 16384, &g_hbuf[p][0][m * 16384],
                         16384u, mb[m]);
                bulk_g2s(smBase + SM_HLO + m * 16384, &g_hbuf[p][1][m * 16384],
                         16384u, mb[m]);
            }
        }

        // xz prefetch for epilogue threads (overlaps bulk copy)
        float2 xz2[4];
        if (tid < 128) {
            const float* xzt = &g_xz[((size_t)t * BB + eb) * G4 + cta * 4 + uh * 2];
#pragma unroll
            for (int gate = 0; gate < 4; gate++)
                xz2[gate] = *(const float2*)&xzt[gate * 512];
        }

        // wait for this warp's 16-row chunk of h
        mbar_wait(mb[mt], (uint32_t)(t & 1));

        // ---- mma: 8 ktiles (this warp's k-quarter), 2 nt, 3 split terms ---
        float c[2][4];
#pragma unroll
        for (int nt = 0; nt < 2; nt++)
#pragma unroll
            for (int q = 0; q < 4; q++) c[nt][q] = 0.f;

#pragma unroll
        for (int ktl = 0; ktl < 8; ktl++) {
            const int kt = kq * 8 + ktl;
            const uint32_t goff = (((uint32_t)(kt * 2 + kbIdx)) ^ rxor) << 4;
            uint4 ah = ldsm4(aRowHi + goff);
            uint4 al = ldsm4(aRowLo + goff);
            uint4 b0 = *(const uint4*)(bP0 + ktl * 512);
            uint4 b1 = *(const uint4*)(bP1 + ktl * 512);
            mma_bf16(c[0], ah.x, ah.y, ah.z, ah.w, b0.x, b0.y);  // AhiBhi
            mma_bf16(c[0], ah.x, ah.y, ah.z, ah.w, b0.z, b0.w);  // AhiBlo
            mma_bf16(c[0], al.x, al.y, al.z, al.w, b0.x, b0.y);  // AloBhi
            mma_bf16(c[1], ah.x, ah.y, ah.z, ah.w, b1.x, b1.y);
            mma_bf16(c[1], ah.x, ah.y, ah.z, ah.w, b1.z, b1.w);
            mma_bf16(c[1], al.x, al.y, al.z, al.w, b1.x, b1.y);
        }

        // store partials: zbuf[kq][row][col]  (even stride -> 8B aligned)
#pragma unroll
        for (int nt = 0; nt < 2; nt++) {
            int r0 = mt * 16 + g, cc = nt * 8 + tq * 2;
            float2 v01 = {c[nt][0], c[nt][1]};
            float2 v23 = {c[nt][2], c[nt][3]};
            *(float2*)&zb[(kq * 64 + r0) * Z_S + cc] = v01;
            *(float2*)&zb[(kq * 64 + r0 + 8) * Z_S + cc] = v23;
        }
        __syncthreads();   // zbuf partials ready (all 16 warps)

        // ---- epilogue: threads 0..127, thread = (batch, unit-half) ----
        // Warps 4..15 skip everything below and run ahead to the next
        // iteration's mbar_wait (parks on the chunk mbarrier; the mbar can
        // only flip after tid0 passes the grid barrier and issues new bulk
        // copies, so zbuf/A-image WAR hazards are transitively protected).
        if (tid < 128) {
            float q[4][2];
#pragma unroll
            for (int gate = 0; gate < 4; gate++) {
                q[gate][0] = xz2[gate].x;
                q[gate][1] = xz2[gate].y;
#pragma unroll
                for (int kk = 0; kk < 4; kk++) {
                    float2 z = *(const float2*)&zb[(kk * 64 + eb) * Z_S + gate * 4 + uh * 2];
                    q[gate][0] += z.x;
                    q[gate][1] += z.y;
                }
            }
            uint16_t hh[2], hl[2];
            float ov[2];
#pragma unroll
            for (int u = 0; u < 2; u++) {
                float ig = 1.f / (1.f + __expf(-q[0][u]));
                float fg = 1.f / (1.f + __expf(-q[1][u]));
                float og = 1.f / (1.f + __expf(-q[3][u]));
                cst[u] = fg * cst[u] + ig * q[2][u];
                float h = og * cst[u];
                split_bf16(h, hh[u], hl[u]);
                ov[u] = tanhf(h);
            }
            unsigned vhi = ((uint32_t)hh[1] << 16) | hh[0];
            unsigned vlo = ((uint32_t)hl[1] << 16) | hl[0];
            const int pn = p ^ 1;
            // swizzled h-image store: row=eb, granule=(cta>>1)^(eb&7),
            // 8B half=(cta&1), 4B quarter=uh
            uint32_t off = (uint32_t)eb * 1024 +
                           ((((uint32_t)cta >> 1) ^ ((uint32_t)eb & 7)) << 4) +
                           ((uint32_t)cta & 1) * 8 + (uint32_t)uh * 4;
            __stcg((unsigned*)(&g_hbuf[pn][0][0] + off), vhi);
            __stcg((unsigned*)(&g_hbuf[pn][1][0] + off), vlo);
            float2 o2 = {ov[0], ov[1]};
            *(float2*)&out[((size_t)eb * TT + t) * UU + cta * 4 + uh * 2] = o2;

            // h-stores of this CTA complete among the 128 producers
            asm volatile("bar.sync 5, 128;" ::: "memory");

            // grid barrier: proven monotonic atomic counter; only tid0 waits
            if (tid == 0) {
                __threadfence();
                unsigned arrived = atomicAdd(&g_barcount, 1u) + 1u;
                unsigned target = (unsigned)(t + 1) * (unsigned)NCTA;
                if (arrived < target) {
                    while (*((volatile unsigned*)&g_barcount) < target) { }
                }
            }
        }
        // no trailing __syncthreads: next-iteration ordering is enforced by
        // the chunk mbarriers (tid0 issues bulk copies only after the grid
        // barrier passes).
    }
}

// ---------------- launch ----------------
extern "C" void kernel_launch(void* const* d_in, const int* in_sizes, int n_in,
                              void* d_out, int out_size) {
    const float* x    = (const float*)d_in[0];   // [64,1024,256]
    const float* w    = (const float*)d_in[1];   // [256,2048]
    const float* rw   = (const float*)d_in[2];   // [512,2048]
    const float* bias = (const float*)d_in[3];   // [2048]
    float* out = (float*)d_out;                  // [64,1024,512]
    (void)in_sizes; (void)n_in; (void)out_size;

    // 4 launches/iteration; lstm_rec is the 4th (ncu captures launch #4)
    prep_misc<<<4608, 256>>>(x, w);
    prep_B<<<NCTA, 256>>>(rw);

    static int smem_set = 0;
    if (!smem_set) {
        cudaFuncSetAttribute(xz_mma, cudaFuncAttributeMaxDynamicSharedMemorySize,
                             X1_SMEM);
        cudaFuncSetAttribute(lstm_rec, cudaFuncAttributeMaxDynamicSharedMemorySize,
                             SMEM_DYN);
        smem_set = 1;
    }

    dim3 g1(G4 / 128, (BB * TT) / 128);   // (16, 512)
    xz_mma<<<g1, 256, X1_SMEM>>>(bias);

    lstm_rec<<<NCTA, THR2, SMEM_DYN>>>(out);
}